// round 1
// baseline (speedup 1.0000x reference)
#include <cuda_runtime.h>

#define HH 128
#define WW 128
#define BB 64
#define OO 32
#define PITCH 132          // pad: bank = (4*y + x) % 32 -> spreads slanted sample lines
#define TPB 256

__global__ __launch_bounds__(TPB) void dalayer_kernel(
    const float* __restrict__ X,
    const float* __restrict__ eps,
    const float* __restrict__ tmin,
    const float* __restrict__ tmax,
    float* __restrict__ out)
{
    extern __shared__ float simg[];   // [128][PITCH]

    const int bx = blockIdx.x;
    const int o = bx & (OO - 1);      // consecutive CTAs share image b -> L2 reuse
    const int b = bx >> 5;

    // ---- stage image b into padded smem (coalesced float4 reads) ----
    const float4* src = reinterpret_cast<const float4*>(X + (size_t)b * HH * WW);
    #pragma unroll
    for (int i = threadIdx.x; i < HH * WW / 4; i += TPB) {
        const int row  = i >> 5;      // 32 float4 per 128-float row
        const int col4 = (i & 31) << 2;
        float4 v = src[i];
        float* dst = simg + row * PITCH + col4;
        dst[0] = v.x; dst[1] = v.y; dst[2] = v.z; dst[3] = v.w;
    }

    // ---- affine params for this o (redundant per-thread, trivial cost) ----
    float th[7];
    #pragma unroll
    for (int i = 0; i < 7; i++) {
        const float mn = tmin[i];
        th[i] = fmaf(tmax[i] - mn, eps[o * 7 + i], mn);
    }
    float s, c;
    sincosf(th[0], &s, &c);
    const float sx = th[1], sy = th[2], pX = th[3], pY = th[4], tx = th[5], ty = th[6];
    const float a00 = c * sx - s * pY;
    const float a01 = c * pX - s * sy;
    const float a10 = s * sx + c * pY;
    const float a11 = s * pX + c * sy;
    // px = (a00*Xg + a01*Yg + tx + 1)*63.5 with Xg = -1 + x*(2/127)
    //    = a00*x + a01*y + 63.5*(tx + 1 - a00 - a01)    [ (2/127)*63.5 == 1 exactly ]
    const float offx = 63.5f * (tx + 1.0f - a00 - a01);
    const float offy = 63.5f * (ty + 1.0f - a10 - a11);

    __syncthreads();

    float* __restrict__ outp = out + (size_t)(o * BB + b) * (HH * WW);

    #pragma unroll 4
    for (int it = 0; it < HH * WW / TPB; it++) {
        const int p = it * TPB + threadIdx.x;
        const int x = p & (WW - 1);
        const int y = p >> 7;

        const float px = fmaf(a00, (float)x, fmaf(a01, (float)y, offx));
        const float py = fmaf(a10, (float)x, fmaf(a11, (float)y, offy));

        const int x0 = __float2int_rd(px);
        const int y0 = __float2int_rd(py);
        const float wx = px - (float)x0;
        const float wy = py - (float)y0;

        const int x0c = min(max(x0,     0), WW - 1);
        const int x1c = min(max(x0 + 1, 0), WW - 1);
        const int y0c = min(max(y0,     0), HH - 1);
        const int y1c = min(max(y0 + 1, 0), HH - 1);

        const float* r0 = simg + y0c * PITCH;
        const float* r1 = simg + y1c * PITCH;
        const float Ia = r0[x0c];
        const float Ic = r0[x1c];
        const float Ib = r1[x0c];
        const float Id = r1[x1c];

        const float t0 = fmaf(wx, Ic - Ia, Ia);
        const float t1 = fmaf(wx, Id - Ib, Ib);
        outp[p] = fmaf(wy, t1 - t0, t0);
    }
}

extern "C" void kernel_launch(void* const* d_in, const int* in_sizes, int n_in,
                              void* d_out, int out_size)
{
    const float* X    = (const float*)d_in[0];
    const float* eps  = (const float*)d_in[1];
    const float* tmin = (const float*)d_in[2];
    const float* tmax = (const float*)d_in[3];
    float* out = (float*)d_out;

    const int smem_bytes = HH * PITCH * sizeof(float);  // 67584
    static bool attr_set = false;
    if (!attr_set) {
        cudaFuncSetAttribute(dalayer_kernel,
                             cudaFuncAttributeMaxDynamicSharedMemorySize, smem_bytes);
        attr_set = true;
    }

    dalayer_kernel<<<BB * OO, TPB, smem_bytes>>>(X, eps, tmin, tmax, out);
}

// round 3
// speedup vs baseline: 1.0039x; 1.0039x over previous
#include <cuda_runtime.h>

#define HH 128
#define WW 128
#define BB 64
#define OO 32
#define PITCH 133          // 133 mod 32 = 5 (odd): high-angle lane stride covers all 32 banks
#define TPB 256

__global__ __launch_bounds__(TPB) void dalayer_kernel(
    const float* __restrict__ X,
    const float* __restrict__ eps,
    const float* __restrict__ tmin,
    const float* __restrict__ tmax,
    float* __restrict__ out)
{
    extern __shared__ float simg[];   // [128][PITCH]

    const int tid = threadIdx.x;
    const int bx = blockIdx.x;
    const int o = bx & (OO - 1);      // consecutive CTAs share image b -> L2 reuse
    const int b = bx >> 5;

    // ---- stage image b into padded smem (float4 gmem reads, scalar STS) ----
    const float4* src = reinterpret_cast<const float4*>(X + (size_t)b * HH * WW);
    #pragma unroll
    for (int i = tid; i < HH * WW / 4; i += TPB) {
        const int row  = i >> 5;      // 32 float4 per 128-float row
        const int col4 = (i & 31) << 2;
        float4 v = src[i];
        float* dst = simg + row * PITCH + col4;
        dst[0] = v.x; dst[1] = v.y; dst[2] = v.z; dst[3] = v.w;
    }

    // ---- affine params for this o (redundant per-thread, trivial cost) ----
    float th[7];
    #pragma unroll
    for (int i = 0; i < 7; i++) {
        const float mn = tmin[i];
        th[i] = fmaf(tmax[i] - mn, eps[o * 7 + i], mn);
    }
    float s, c;
    sincosf(th[0], &s, &c);
    const float sx = th[1], sy = th[2], pX = th[3], pY = th[4], tx = th[5], ty = th[6];
    const float a00 = c * sx - s * pY;
    const float a01 = c * pX - s * sy;
    const float a10 = s * sx + c * pY;
    const float a11 = s * pX + c * sy;
    // px = (a00*Xg + a01*Yg + tx + 1)*63.5 with Xg = -1 + x*(2/127)
    //    = a00*x + a01*y + 63.5*(tx + 1 - a00 - a01)    [ (2/127)*63.5 == 1 exactly ]
    const float offx = 63.5f * (tx + 1.0f - a00 - a01);
    const float offy = 63.5f * (ty + 1.0f - a10 - a11);

    __syncthreads();

    // thread owns fixed x; walks y in steps of 2 (TPB/WW rows per iter)
    const int x    = tid & (WW - 1);
    const int yini = tid >> 7;

    float px = fmaf(a01, (float)yini, fmaf(a00, (float)x, offx));
    float py = fmaf(a11, (float)yini, fmaf(a10, (float)x, offy));
    const float dpx = 2.0f * a01;
    const float dpy = 2.0f * a11;

    float* __restrict__ outp = out + (size_t)(o * BB + b) * (HH * WW) + tid;

    #pragma unroll 8
    for (int it = 0; it < HH / 2; it++) {
        // clamp coordinates (not indices): x1=x0+1 always valid -> imm-offset LDS
        const float cx = fminf(fmaxf(px, 0.0f), 126.99999f);
        const float cy = fminf(fmaxf(py, 0.0f), 126.99999f);
        const int x0 = (int)cx;               // cx >= 0 -> trunc == floor
        const int y0 = (int)cy;
        const float wx = cx - (float)x0;
        const float wy = cy - (float)y0;

        const float* rr = simg + (y0 * PITCH + x0);
        const float Ia = rr[0];
        const float Ic = rr[1];
        const float Ib = rr[PITCH];
        const float Id = rr[PITCH + 1];

        const float t0 = fmaf(wx, Ic - Ia, Ia);
        const float t1 = fmaf(wx, Id - Ib, Ib);
        outp[it * TPB] = fmaf(wy, t1 - t0, t0);

        px += dpx;
        py += dpy;
    }
}

extern "C" void kernel_launch(void* const* d_in, const int* in_sizes, int n_in,
                              void* d_out, int out_size)
{
    const float* X    = (const float*)d_in[0];
    const float* eps  = (const float*)d_in[1];
    const float* tmin = (const float*)d_in[2];
    const float* tmax = (const float*)d_in[3];
    float* out = (float*)d_out;

    const int smem_bytes = HH * PITCH * sizeof(float);  // 68096
    static bool attr_set = false;
    if (!attr_set) {
        cudaFuncSetAttribute(dalayer_kernel,
                             cudaFuncAttributeMaxDynamicSharedMemorySize, smem_bytes);
        attr_set = true;
    }

    dalayer_kernel<<<BB * OO, TPB, smem_bytes>>>(X, eps, tmin, tmax, out);
}